// round 2
// baseline (speedup 1.0000x reference)
#include <cuda_runtime.h>
#include <cstdint>

#define Bq 1024
#define Lq 100
#define Hq 256
#define Oq 256
#define NBLK 148
#define NTHR 256

typedef unsigned long long u64;

// ---------------- static scratch ----------------
__device__ float g_enc_proj[Bq * Lq * Hq];
__device__ float g_Wp0[1024 * 768];
__device__ float g_Wp1[1024 * 512];
__device__ float g_b0p[1024];
__device__ float g_b1p[1024];
__device__ float g_h0a[Bq * Hq], g_h0b[Bq * Hq];
__device__ float g_h1a[Bq * Hq], g_h1b[Bq * Hq];
__device__ float g_c0[Bq * Hq], g_c1[Bq * Hq];
__device__ float g_ctx[Bq * Hq], g_ctx_att[Bq * Hq];
__device__ float g_logit[Bq * Oq], g_Q[Bq * Oq];
__device__ unsigned g_count;

// ---------------- f32x2 packed helpers ----------------
__device__ __forceinline__ u64 pk2(float lo, float hi) {
    u64 r; asm("mov.b64 %0, {%1, %2};" : "=l"(r) : "f"(lo), "f"(hi)); return r;
}
__device__ __forceinline__ float2 up2(u64 v) {
    float2 r; asm("mov.b64 {%0, %1}, %2;" : "=f"(r.x), "=f"(r.y) : "l"(v)); return r;
}
__device__ __forceinline__ void fma2(u64& d, u64 a, u64 b) {
    asm("fma.rn.f32x2 %0, %1, %2, %0;" : "+l"(d) : "l"(a), "l"(b));
}

// ---------------- grid barrier (release/acquire, monotonic counter) ----------
__device__ __forceinline__ void gsync(unsigned target) {
    __syncthreads();
    if (threadIdx.x == 0) {
        unsigned o;
        asm volatile("atom.add.release.gpu.u32 %0, [%1], 1;"
                     : "=r"(o) : "l"(&g_count) : "memory");
        unsigned cur;
        do {
            asm volatile("ld.acquire.gpu.u32 %0, [%1];"
                         : "=r"(cur) : "l"(&g_count) : "memory");
        } while ((int)(cur - target) < 0);
    }
    __syncthreads();
}

// ---------------- shared pool ----------------
struct GemmSmem { float As[16][136]; float Ws[16][72]; };
struct AttSmem { float hv[256]; float sc[128]; float red[128]; };
union SPool {
    GemmSmem g;
    AttSmem a;
    float fin[256];
};

__device__ __forceinline__ float sigm(float x) { return 1.f / (1.f + __expf(-x)); }

// ---------------- GEMM tile 128x64, K in 256-wide segments, f32x2 math ------
// mode 0: C store (+bias), 1: tanh(C+bias) store, 2: LSTM cell epilogue
__device__ void gemm128(SPool& sp, const int* gidx, int bm, int bn,
                        const float* A0, const float* A1, const float* A2, int Kt,
                        bool use_gather,
                        const float* __restrict__ W, const float* __restrict__ bias,
                        int mode, float* C, int ldC, float* cst, float* hout) {
    const int tid = threadIdx.x;
    const int tx = tid & 15, ty = tid >> 4;
    const int kq = (tid & 3) * 4;
    const int rA = tid >> 2;
    u64 acc[4][4];
#pragma unroll
    for (int i = 0; i < 4; i++)
#pragma unroll
        for (int j = 0; j < 4; j++) acc[i][j] = 0ull;

    float4 pa0, pa1, pw;
    // prefetch chunk 0
    {
        const float* Ab = A0;
        int kc = kq;
        if (use_gather) {
            pa0 = *(const float4*)(Ab + (size_t)gidx[rA] * Hq + kc);
            pa1 = *(const float4*)(Ab + (size_t)gidx[rA + 64] * Hq + kc);
        } else {
            pa0 = *(const float4*)(Ab + (size_t)(bm + rA) * Hq + kc);
            pa1 = *(const float4*)(Ab + (size_t)(bm + rA + 64) * Hq + kc);
        }
        pw = *(const float4*)(W + (size_t)(bn + rA) * Kt + kq);
    }

    for (int k0 = 0; k0 < Kt; k0 += 16) {
        // store staged chunk
        sp.g.As[kq + 0][rA] = pa0.x; sp.g.As[kq + 1][rA] = pa0.y;
        sp.g.As[kq + 2][rA] = pa0.z; sp.g.As[kq + 3][rA] = pa0.w;
        sp.g.As[kq + 0][rA + 64] = pa1.x; sp.g.As[kq + 1][rA + 64] = pa1.y;
        sp.g.As[kq + 2][rA + 64] = pa1.z; sp.g.As[kq + 3][rA + 64] = pa1.w;
        sp.g.Ws[kq + 0][rA] = pw.x; sp.g.Ws[kq + 1][rA] = pw.y;
        sp.g.Ws[kq + 2][rA] = pw.z; sp.g.Ws[kq + 3][rA] = pw.w;
        __syncthreads();
        // prefetch next chunk
        int kn = k0 + 16;
        if (kn < Kt) {
            int seg = kn >> 8;
            const float* Ab = (seg == 0) ? A0 : (seg == 1 ? A1 : A2);
            int kc = (kn & 255) + kq;
            if (use_gather && seg == 0) {
                pa0 = *(const float4*)(Ab + (size_t)gidx[rA] * Hq + kc);
                pa1 = *(const float4*)(Ab + (size_t)gidx[rA + 64] * Hq + kc);
            } else {
                pa0 = *(const float4*)(Ab + (size_t)(bm + rA) * Hq + kc);
                pa1 = *(const float4*)(Ab + (size_t)(bm + rA + 64) * Hq + kc);
            }
            pw = *(const float4*)(W + (size_t)(bn + rA) * Kt + kn + kq);
        }
#pragma unroll
        for (int kk = 0; kk < 16; kk++) {
            float4 wv = *(const float4*)&sp.g.Ws[kk][tx * 4];
            u64 wd0 = pk2(wv.x, wv.x), wd1 = pk2(wv.y, wv.y);
            u64 wd2 = pk2(wv.z, wv.z), wd3 = pk2(wv.w, wv.w);
            ulonglong2 aA = *(const ulonglong2*)&sp.g.As[kk][ty * 8];
            ulonglong2 aB = *(const ulonglong2*)&sp.g.As[kk][ty * 8 + 4];
            fma2(acc[0][0], aA.x, wd0); fma2(acc[0][1], aA.x, wd1);
            fma2(acc[0][2], aA.x, wd2); fma2(acc[0][3], aA.x, wd3);
            fma2(acc[1][0], aA.y, wd0); fma2(acc[1][1], aA.y, wd1);
            fma2(acc[1][2], aA.y, wd2); fma2(acc[1][3], aA.y, wd3);
            fma2(acc[2][0], aB.x, wd0); fma2(acc[2][1], aB.x, wd1);
            fma2(acc[2][2], aB.x, wd2); fma2(acc[2][3], aB.x, wd3);
            fma2(acc[3][0], aB.y, wd0); fma2(acc[3][1], aB.y, wd1);
            fma2(acc[3][2], aB.y, wd2); fma2(acc[3][3], aB.y, wd3);
        }
        __syncthreads();
    }

    if (mode == 2) {
        int h = (bn >> 2) + tx;
        float bv0 = bias[bn + tx * 4 + 0], bv1 = bias[bn + tx * 4 + 1];
        float bv2 = bias[bn + tx * 4 + 2], bv3 = bias[bn + tx * 4 + 3];
#pragma unroll
        for (int i2 = 0; i2 < 4; i2++) {
            float2 gi = up2(acc[i2][0]), gf = up2(acc[i2][1]);
            float2 gg = up2(acc[i2][2]), go = up2(acc[i2][3]);
            int b = bm + ty * 8 + i2 * 2;
            {
                float I = sigm(gi.x + bv0), F = sigm(gf.x + bv1);
                float G = tanhf(gg.x + bv2), O_ = sigm(go.x + bv3);
                int idx = b * Hq + h;
                float cn = F * cst[idx] + I * G;
                cst[idx] = cn; hout[idx] = O_ * tanhf(cn);
            }
            {
                float I = sigm(gi.y + bv0), F = sigm(gf.y + bv1);
                float G = tanhf(gg.y + bv2), O_ = sigm(go.y + bv3);
                int idx = (b + 1) * Hq + h;
                float cn = F * cst[idx] + I * G;
                cst[idx] = cn; hout[idx] = O_ * tanhf(cn);
            }
        }
    } else {
#pragma unroll
        for (int i2 = 0; i2 < 4; i2++) {
            int b = bm + ty * 8 + i2 * 2;
#pragma unroll
            for (int j = 0; j < 4; j++) {
                float2 v = up2(acc[i2][j]);
                int n = bn + tx * 4 + j;
                float ve = v.x, vo = v.y;
                if (bias) { ve += bias[n]; vo += bias[n]; }
                if (mode == 1) { ve = tanhf(ve); vo = tanhf(vo); }
                C[(size_t)b * ldC + n] = ve;
                C[(size_t)(b + 1) * ldC + n] = vo;
            }
        }
    }
}

// ---------------- GEMM tile 64x64 ----------------
__device__ void gemm64(SPool& sp, int bm, int bn,
                       const float* A0, const float* A1, int Kt,
                       const float* __restrict__ W, const float* __restrict__ bias,
                       int mode, float* C) {
    const int tid = threadIdx.x;
    const int tx = tid & 15, ty = tid >> 4;
    const int kq = (tid & 3) * 4;
    const int rA = tid >> 2;
    u64 acc[2][4];
#pragma unroll
    for (int i = 0; i < 2; i++)
#pragma unroll
        for (int j = 0; j < 4; j++) acc[i][j] = 0ull;

    float4 pa, pw;
    pa = *(const float4*)(A0 + (size_t)(bm + rA) * Hq + kq);
    pw = *(const float4*)(W + (size_t)(bn + rA) * Kt + kq);

    for (int k0 = 0; k0 < Kt; k0 += 16) {
        sp.g.As[kq + 0][rA] = pa.x; sp.g.As[kq + 1][rA] = pa.y;
        sp.g.As[kq + 2][rA] = pa.z; sp.g.As[kq + 3][rA] = pa.w;
        sp.g.Ws[kq + 0][rA] = pw.x; sp.g.Ws[kq + 1][rA] = pw.y;
        sp.g.Ws[kq + 2][rA] = pw.z; sp.g.Ws[kq + 3][rA] = pw.w;
        __syncthreads();
        int kn = k0 + 16;
        if (kn < Kt) {
            int seg = kn >> 8;
            const float* Ab = (seg == 0) ? A0 : A1;
            int kc = (kn & 255) + kq;
            pa = *(const float4*)(Ab + (size_t)(bm + rA) * Hq + kc);
            pw = *(const float4*)(W + (size_t)(bn + rA) * Kt + kn + kq);
        }
#pragma unroll
        for (int kk = 0; kk < 16; kk++) {
            float4 wv = *(const float4*)&sp.g.Ws[kk][tx * 4];
            u64 wd0 = pk2(wv.x, wv.x), wd1 = pk2(wv.y, wv.y);
            u64 wd2 = pk2(wv.z, wv.z), wd3 = pk2(wv.w, wv.w);
            ulonglong2 aA = *(const ulonglong2*)&sp.g.As[kk][ty * 4];
            fma2(acc[0][0], aA.x, wd0); fma2(acc[0][1], aA.x, wd1);
            fma2(acc[0][2], aA.x, wd2); fma2(acc[0][3], aA.x, wd3);
            fma2(acc[1][0], aA.y, wd0); fma2(acc[1][1], aA.y, wd1);
            fma2(acc[1][2], aA.y, wd2); fma2(acc[1][3], aA.y, wd3);
        }
        __syncthreads();
    }
#pragma unroll
    for (int i2 = 0; i2 < 2; i2++) {
        int b = bm + ty * 4 + i2 * 2;
#pragma unroll
        for (int j = 0; j < 4; j++) {
            float2 v = up2(acc[i2][j]);
            int n = bn + tx * 4 + j;
            float ve = v.x, vo = v.y;
            if (bias) { ve += bias[n]; vo += bias[n]; }
            if (mode == 1) { ve = tanhf(ve); vo = tanhf(vo); }
            C[(size_t)b * 256 + n] = ve;
            C[(size_t)(b + 1) * 256 + n] = vo;
        }
    }
}

// ---------------- attention, one batch row per call ----------------
__device__ void attention_row(SPool& sp, int b, const float* __restrict__ h1,
                              const float* __restrict__ ep, const float* __restrict__ eo,
                              float* __restrict__ ctx_att) {
    int tid = threadIdx.x, warp = tid >> 5, lane = tid & 31;
    sp.a.hv[tid] = h1[b * Hq + tid];
    if (tid < 128) sp.a.sc[tid] = -1e30f;
    __syncthreads();
    for (int l = warp; l < Lq; l += 8) {
        const float* p = ep + ((size_t)b * Lq + l) * Hq;
        float s = 0.f;
#pragma unroll
        for (int k = 0; k < 8; k++) s += sp.a.hv[lane + k * 32] * p[lane + k * 32];
#pragma unroll
        for (int o = 16; o; o >>= 1) s += __shfl_xor_sync(0xFFFFFFFFu, s, o);
        if (!lane) sp.a.sc[l] = s;
    }
    __syncthreads();
    if (tid < 128) sp.a.red[tid] = sp.a.sc[tid];
    __syncthreads();
    for (int s = 64; s; s >>= 1) {
        if (tid < s) sp.a.red[tid] = fmaxf(sp.a.red[tid], sp.a.red[tid + s]);
        __syncthreads();
    }
    float mx = sp.a.red[0];
    __syncthreads();
    if (tid < 128) {
        float e = (tid < Lq) ? __expf(sp.a.sc[tid] - mx) : 0.f;
        sp.a.sc[tid] = e; sp.a.red[tid] = e;
    }
    __syncthreads();
    for (int s = 64; s; s >>= 1) {
        if (tid < s) sp.a.red[tid] += sp.a.red[tid + s];
        __syncthreads();
    }
    float inv = 1.f / sp.a.red[0];
    float acc = 0.f;
    const float* p = eo + (size_t)b * Lq * Hq + tid;
    for (int l = 0; l < Lq; l++) acc += sp.a.sc[l] * p[(size_t)l * Hq];
    ctx_att[b * Hq + tid] = acc * inv;
    __syncthreads();
}

// ---------------- finalize one batch row ----------------
__device__ void finalize_row(SPool& sp, int b, int t, const float* __restrict__ logit,
                             const float* __restrict__ Q, const int* __restrict__ actions,
                             float* __restrict__ out) {
    int tid = threadIdx.x;
    float x = logit[b * 256 + tid];
    sp.fin[tid] = x; __syncthreads();
    for (int s = 128; s; s >>= 1) {
        if (tid < s) sp.fin[tid] = fmaxf(sp.fin[tid], sp.fin[tid + s]);
        __syncthreads();
    }
    float mx = sp.fin[0]; __syncthreads();
    float e = __expf(x - mx);
    sp.fin[tid] = e; __syncthreads();
    for (int s = 128; s; s >>= 1) {
        if (tid < s) sp.fin[tid] += sp.fin[tid + s];
        __syncthreads();
    }
    float pi = e / sp.fin[0]; __syncthreads();
    out[(size_t)Bq * Lq + ((size_t)b * Lq + t) * Oq + tid] = pi;
    sp.fin[tid] = pi * Q[b * 256 + tid]; __syncthreads();
    for (int s = 128; s; s >>= 1) {
        if (tid < s) sp.fin[tid] += sp.fin[tid + s];
        __syncthreads();
    }
    if (!tid) {
        out[(size_t)Bq * Lq + (size_t)Bq * Lq * Oq + b * Lq + t] = sp.fin[0];
        out[b * Lq + t] = (float)actions[b * Lq + t];
    }
    __syncthreads();
}

// ---------------- persistent mega-kernel ----------------
__global__ void __launch_bounds__(NTHR)
mega(const float* __restrict__ enc_out, const float* __restrict__ enc_h,
     const float* __restrict__ enc_c, const float* __restrict__ emb,
     const float* __restrict__ Wih0, const float* __restrict__ Whh0,
     const float* __restrict__ bih0, const float* __restrict__ bhh0,
     const float* __restrict__ Wih1, const float* __restrict__ Whh1,
     const float* __restrict__ bih1, const float* __restrict__ bhh1,
     const float* __restrict__ Wa, const float* __restrict__ Wconcat,
     const float* __restrict__ Wout, const float* __restrict__ Wcrit,
     const float* __restrict__ bcrit, const int* __restrict__ actions,
     float* __restrict__ out) {
    __shared__ SPool sp;
    __shared__ int gidx[128];
    const int bid = blockIdx.x, tid = threadIdx.x;
    unsigned bt = 0;

    // ---- phase 0: weight permute (gate-interleaved) + state init ----
    for (int idx = bid * NTHR + tid; idx < 1024 * 768; idx += NBLK * NTHR) {
        int n = idx / 768, k = idx - n * 768;
        int h = n >> 2, g = n & 3, orow = g * 256 + h;
        g_Wp0[idx] = (k < 512) ? Wih0[orow * 512 + k] : Whh0[orow * 256 + (k - 512)];
    }
    for (int idx = bid * NTHR + tid; idx < 1024 * 512; idx += NBLK * NTHR) {
        int n = idx / 512, k = idx - n * 512;
        int h = n >> 2, g = n & 3, orow = g * 256 + h;
        g_Wp1[idx] = (k < 256) ? Wih1[orow * 256 + k] : Whh1[orow * 256 + (k - 256)];
    }
    for (int idx = bid * NTHR + tid; idx < 1024; idx += NBLK * NTHR) {
        int h = idx >> 2, g = idx & 3, orow = g * 256 + h;
        g_b0p[idx] = bih0[orow] + bhh0[orow];
        g_b1p[idx] = bih1[orow] + bhh1[orow];
    }
    for (int idx = bid * NTHR + tid; idx < Bq * Hq; idx += NBLK * NTHR) {
        g_h0a[idx] = enc_h[idx]; g_h1a[idx] = enc_h[Bq * Hq + idx];
        g_c0[idx] = enc_c[idx];  g_c1[idx] = enc_c[Bq * Hq + idx];
        int b = idx >> 8, hh = idx & 255;
        const float* p = enc_out + (size_t)b * Lq * Hq + hh;
        float s = 0.f;
        for (int l = 0; l < Lq; l++) s += p[(size_t)l * Hq];
        g_ctx[idx] = s * (1.0f / Lq);
    }
    bt += NBLK; gsync(bt);

    // ---- enc_proj = enc_out @ Wa^T  [102400 x 256] ----
    for (int tile = bid; tile < 3200; tile += NBLK) {
        int bm = (tile >> 2) * 128, bn = (tile & 3) * 64;
        gemm128(sp, gidx, bm, bn, enc_out, nullptr, nullptr, 256, false,
                Wa, nullptr, 0, g_enc_proj, 256, nullptr, nullptr);
    }
    bt += NBLK; gsync(bt);

    float *h0c = g_h0a, *h0n = g_h0b, *h1c = g_h1a, *h1n = g_h1b;
    for (int t = 0; t < Lq; t++) {
        // phase 1: LSTM0 gates GEMM + cell epilogue
        if (bid < 128) {
            int bm = (bid >> 4) * 128, bn = (bid & 15) * 64;
            if (tid < 128)
                gidx[tid] = (t == 0) ? 0 : actions[(bm + tid) * Lq + (t - 1)];
            __syncthreads();
            gemm128(sp, gidx, bm, bn, emb, g_ctx, h0c, 768, true,
                    g_Wp0, g_b0p, 2, nullptr, 0, g_c0, h0n);
        }
        bt += NBLK; gsync(bt);
        // phase 2: LSTM1
        if (bid < 128) {
            int bm = (bid >> 4) * 128, bn = (bid & 15) * 64;
            gemm128(sp, gidx, bm, bn, h0n, h1c, nullptr, 512, false,
                    g_Wp1, g_b1p, 2, nullptr, 0, g_c1, h1n);
        }
        bt += NBLK; gsync(bt);
        // phase 3: attention
        for (int b = bid; b < Bq; b += NBLK)
            attention_row(sp, b, h1n, g_enc_proj, enc_out, g_ctx_att);
        bt += NBLK; gsync(bt);
        // phase 4: new_ctx = tanh([h1|ctx_att] @ Wconcat^T)
        if (bid < 64) {
            int bm = (bid >> 2) * 64, bn = (bid & 3) * 64;
            gemm64(sp, bm, bn, h1n, g_ctx_att, 512, Wconcat, nullptr, 1, g_ctx);
        }
        bt += NBLK; gsync(bt);
        // phase 5: logit = ctx @ Wout^T
        if (bid < 64) {
            int bm = (bid >> 2) * 64, bn = (bid & 3) * 64;
            gemm64(sp, bm, bn, g_ctx, nullptr, 256, Wout, nullptr, 0, g_logit);
        }
        bt += NBLK; gsync(bt);
        // phase 6: Q = logit @ Wcrit^T + bcrit
        if (bid < 64) {
            int bm = (bid >> 2) * 64, bn = (bid & 3) * 64;
            gemm64(sp, bm, bn, g_logit, nullptr, 256, Wcrit, bcrit, 0, g_Q);
        }
        bt += NBLK; gsync(bt);
        // phase 7: finalize (no barrier needed: next write to logit is 4 barriers away)
        for (int b = bid; b < Bq; b += NBLK)
            finalize_row(sp, b, t, g_logit, g_Q, actions, out);
        // swap ping-pong state
        float* tmp = h0c; h0c = h0n; h0n = tmp;
        tmp = h1c; h1c = h1n; h1n = tmp;
    }
}

__global__ void reset_k() { g_count = 0; }

// ---------------- host ----------------
extern "C" void kernel_launch(void* const* d_in, const int* in_sizes, int n_in,
                              void* d_out, int out_size) {
    const float* enc_out = (const float*)d_in[0];
    const float* enc_h   = (const float*)d_in[1];
    const float* enc_c   = (const float*)d_in[2];
    const float* emb     = (const float*)d_in[3];
    const float* Wih0    = (const float*)d_in[4];
    const float* Whh0    = (const float*)d_in[5];
    const float* bih0    = (const float*)d_in[6];
    const float* bhh0    = (const float*)d_in[7];
    const float* Wih1    = (const float*)d_in[8];
    const float* Whh1    = (const float*)d_in[9];
    const float* bih1    = (const float*)d_in[10];
    const float* bhh1    = (const float*)d_in[11];
    const float* Wa      = (const float*)d_in[12];
    const float* Wconcat = (const float*)d_in[13];
    const float* Wout    = (const float*)d_in[14];
    const float* Wcrit   = (const float*)d_in[15];
    const float* bcrit   = (const float*)d_in[16];
    const int*   actions = (const int*)d_in[17];
    float* out = (float*)d_out;

    reset_k<<<1, 1>>>();
    mega<<<NBLK, NTHR>>>(enc_out, enc_h, enc_c, emb,
                         Wih0, Whh0, bih0, bhh0,
                         Wih1, Whh1, bih1, bhh1,
                         Wa, Wconcat, Wout, Wcrit, bcrit, actions, out);
}

// round 3
// speedup vs baseline: 1.0509x; 1.0509x over previous
#include <cuda_runtime.h>
#include <cstdint>

#define Bq 1024
#define Lq 100
#define NBLK 128
#define NTHR 512

typedef unsigned long long u64;

// ---------------- static scratch ----------------
__device__ float g_Wp0[1024 * 768];
__device__ float g_Wp1[1024 * 512];
__device__ float g_b0p[1024], g_b1p[1024];
__device__ float g_WaT[256 * 256];
__device__ float g_h0a[Bq * 256], g_h0b[Bq * 256];
__device__ float g_h1a[Bq * 256], g_h1b[Bq * 256];
__device__ float g_c0[Bq * 256], g_c1[Bq * 256];
__device__ float g_ctx[Bq * 256], g_ctx_att[Bq * 256];
__device__ float g_q[Bq * 256];
__device__ float g_logit[Bq * 256], g_Q[Bq * 256];
__device__ unsigned g_count;

// ---------------- f32x2 helpers ----------------
__device__ __forceinline__ u64 pk2(float lo, float hi) {
    u64 r; asm("mov.b64 %0, {%1, %2};" : "=l"(r) : "f"(lo), "f"(hi)); return r;
}
__device__ __forceinline__ float2 up2(u64 v) {
    float2 r; asm("mov.b64 {%0, %1}, %2;" : "=f"(r.x), "=f"(r.y) : "l"(v)); return r;
}
__device__ __forceinline__ void fma2(u64& d, u64 a, u64 b) {
    asm("fma.rn.f32x2 %0, %1, %2, %0;" : "+l"(d) : "l"(a), "l"(b));
}
__device__ __forceinline__ float sigm(float x) { return 1.f / (1.f + __expf(-x)); }

// ---------------- grid barrier ----------------
__device__ __forceinline__ void gsync(unsigned target) {
    __syncthreads();
    if (threadIdx.x == 0) {
        unsigned o;
        asm volatile("atom.add.release.gpu.u32 %0, [%1], 1;"
                     : "=r"(o) : "l"(&g_count) : "memory");
        unsigned cur;
        do {
            asm volatile("ld.acquire.gpu.u32 %0, [%1];"
                         : "=r"(cur) : "l"(&g_count) : "memory");
        } while ((int)(cur - target) < 0);
    }
    __syncthreads();
}

// ---------------- dynamic shared pool ----------------
struct SPool {
    union {
        struct { float As[16][136]; float Ws[16][72]; } g;
        struct { float q[256]; float sc[128]; float part[512]; float tile[100 * 256]; } a;
        struct { float part[512]; } f;
    };
};

// ---------------- LSTM GEMM: 128x64 tile, gate-interleaved W, cell epilogue --
__device__ void lstm_gemm(SPool* sp, const int* gidx, int bm, int bn,
                          const float* A0, const float* A1, const float* A2, int Kt,
                          bool gather, const float* __restrict__ W,
                          const float* __restrict__ bias,
                          float* __restrict__ cst, float* __restrict__ hout) {
    const int tid = threadIdx.x;
    const int tx = tid & 15, ty = tid >> 4;      // 16 col-groups x 32 row-groups
    const int rA = tid >> 2, kq = (tid & 3) * 4; // A loader: 128 rows x 4 chunks
    const int rW = tid >> 2;                     // W loader (tid<256): 64 rows
    u64 acc[2][4];
#pragma unroll
    for (int i = 0; i < 2; i++)
#pragma unroll
        for (int j = 0; j < 4; j++) acc[i][j] = 0ull;

    float4 pa, pw;
    if (gather) pa = *(const float4*)(A0 + (size_t)gidx[rA] * 256 + kq);
    else        pa = *(const float4*)(A0 + (size_t)(bm + rA) * 256 + kq);
    if (tid < 256) pw = *(const float4*)(W + (size_t)(bn + rW) * Kt + kq);

    for (int k0 = 0; k0 < Kt; k0 += 16) {
        sp->g.As[kq + 0][rA] = pa.x; sp->g.As[kq + 1][rA] = pa.y;
        sp->g.As[kq + 2][rA] = pa.z; sp->g.As[kq + 3][rA] = pa.w;
        if (tid < 256) {
            sp->g.Ws[kq + 0][rW] = pw.x; sp->g.Ws[kq + 1][rW] = pw.y;
            sp->g.Ws[kq + 2][rW] = pw.z; sp->g.Ws[kq + 3][rW] = pw.w;
        }
        __syncthreads();
        int kn = k0 + 16;
        if (kn < Kt) {
            int seg = kn >> 8;
            const float* Ab = (seg == 0) ? A0 : (seg == 1 ? A1 : A2);
            int kc = (kn & 255) + kq;
            if (gather && seg == 0) pa = *(const float4*)(Ab + (size_t)gidx[rA] * 256 + kc);
            else                    pa = *(const float4*)(Ab + (size_t)(bm + rA) * 256 + kc);
            if (tid < 256) pw = *(const float4*)(W + (size_t)(bn + rW) * Kt + kn + kq);
        }
#pragma unroll
        for (int kk = 0; kk < 16; kk++) {
            float4 wv = *(const float4*)&sp->g.Ws[kk][tx * 4];
            u64 wd0 = pk2(wv.x, wv.x), wd1 = pk2(wv.y, wv.y);
            u64 wd2 = pk2(wv.z, wv.z), wd3 = pk2(wv.w, wv.w);
            ulonglong2 av = *(const ulonglong2*)&sp->g.As[kk][ty * 4];
            fma2(acc[0][0], av.x, wd0); fma2(acc[0][1], av.x, wd1);
            fma2(acc[0][2], av.x, wd2); fma2(acc[0][3], av.x, wd3);
            fma2(acc[1][0], av.y, wd0); fma2(acc[1][1], av.y, wd1);
            fma2(acc[1][2], av.y, wd2); fma2(acc[1][3], av.y, wd3);
        }
        __syncthreads();
    }
    // LSTM cell epilogue: cols bn+tx*4+{0..3} = 4 gates of hidden h
    int h = (bn >> 2) + tx;
    float bv0 = bias[bn + tx * 4 + 0], bv1 = bias[bn + tx * 4 + 1];
    float bv2 = bias[bn + tx * 4 + 2], bv3 = bias[bn + tx * 4 + 3];
#pragma unroll
    for (int i2 = 0; i2 < 2; i2++) {
        float2 gi = up2(acc[i2][0]), gf = up2(acc[i2][1]);
        float2 gg = up2(acc[i2][2]), go = up2(acc[i2][3]);
        int b = bm + ty * 4 + i2 * 2;
        {
            float I = sigm(gi.x + bv0), F = sigm(gf.x + bv1);
            float G = tanhf(gg.x + bv2), Og = sigm(go.x + bv3);
            int idx = b * 256 + h;
            float cn = F * cst[idx] + I * G;
            cst[idx] = cn; hout[idx] = Og * tanhf(cn);
        }
        {
            float I = sigm(gi.y + bv0), F = sigm(gf.y + bv1);
            float G = tanhf(gg.y + bv2), Og = sigm(go.y + bv3);
            int idx = (b + 1) * 256 + h;
            float cn = F * cst[idx] + I * G;
            cst[idx] = cn; hout[idx] = Og * tanhf(cn);
        }
    }
}

// ---------------- small GEMM: 64x32 tile ----------------
// mode 0: store (+bias), 1: tanh store
__device__ void gemm_small(SPool* sp, int bm, int bn,
                           const float* A0, const float* A1, int Kt,
                           const float* __restrict__ W, const float* __restrict__ bias,
                           int mode, float* __restrict__ C) {
    const int tid = threadIdx.x;
    const int tx = tid & 15, ty = tid >> 4;      // 16 col-groups(2) x 32 row-pairs
    u64 acc0 = 0ull, acc1 = 0ull;

    float4 pa, pw;
    const int rA = tid >> 2, kq = (tid & 3) * 4;
    if (tid < 256) pa = *(const float4*)(A0 + (size_t)(bm + rA) * 256 + kq);
    if (tid < 128) pw = *(const float4*)(W + (size_t)(bn + rA) * Kt + kq);

    for (int k0 = 0; k0 < Kt; k0 += 16) {
        if (tid < 256) {
            sp->g.As[kq + 0][rA] = pa.x; sp->g.As[kq + 1][rA] = pa.y;
            sp->g.As[kq + 2][rA] = pa.z; sp->g.As[kq + 3][rA] = pa.w;
        }
        if (tid < 128) {
            sp->g.Ws[kq + 0][rA] = pw.x; sp->g.Ws[kq + 1][rA] = pw.y;
            sp->g.Ws[kq + 2][rA] = pw.z; sp->g.Ws[kq + 3][rA] = pw.w;
        }
        __syncthreads();
        int kn = k0 + 16;
        if (kn < Kt) {
            int seg = kn >> 8;
            const float* Ab = (seg == 0) ? A0 : A1;
            int kc = (kn & 255) + kq;
            if (tid < 256) pa = *(const float4*)(Ab + (size_t)(bm + rA) * 256 + kc);
            if (tid < 128) pw = *(const float4*)(W + (size_t)(bn + rA) * Kt + kn + kq);
        }
#pragma unroll
        for (int kk = 0; kk < 16; kk++) {
            float2 wv = *(const float2*)&sp->g.Ws[kk][tx * 2];
            u64 a = *(const u64*)&sp->g.As[kk][ty * 2];
            fma2(acc0, a, pk2(wv.x, wv.x));
            fma2(acc1, a, pk2(wv.y, wv.y));
        }
        __syncthreads();
    }
    int r0 = bm + ty * 2;
#pragma unroll
    for (int j = 0; j < 2; j++) {
        float2 v = up2(j ? acc1 : acc0);
        int n = bn + tx * 2 + j;
        float ve = v.x, vo = v.y;
        if (bias) { ve += bias[n]; vo += bias[n]; }
        if (mode == 1) { ve = tanhf(ve); vo = tanhf(vo); }
        C[(size_t)r0 * 256 + n] = ve;
        C[(size_t)(r0 + 1) * 256 + n] = vo;
    }
}

// ---------------- fused attention, one batch row (512 threads) ---------------
__device__ void attention_row(SPool* sp, int b, const float* __restrict__ q,
                              const float* __restrict__ eo, float* __restrict__ ctx_att) {
    const int tid = threadIdx.x, w = tid >> 5, lane = tid & 31;
    if (tid < 256) sp->a.q[tid] = q[b * 256 + tid];
    if (tid >= 100 && tid < 128) sp->a.sc[tid] = -1e30f;
    __syncthreads();

    float4 q0 = *(const float4*)&sp->a.q[lane * 4];
    float4 q1 = *(const float4*)&sp->a.q[128 + lane * 4];
    const float* rowbase = eo + (size_t)b * Lq * 256;

    int l = w;
    float4 v0, v1;
    {
        const float* p = rowbase + (size_t)l * 256;
        v0 = *(const float4*)(p + lane * 4);
        v1 = *(const float4*)(p + 128 + lane * 4);
    }
    while (l < Lq) {
        int ln = l + 16;
        float4 n0, n1;
        if (ln < Lq) {
            const float* p = rowbase + (size_t)ln * 256;
            n0 = *(const float4*)(p + lane * 4);
            n1 = *(const float4*)(p + 128 + lane * 4);
        }
        *(float4*)&sp->a.tile[l * 256 + lane * 4] = v0;
        *(float4*)&sp->a.tile[l * 256 + 128 + lane * 4] = v1;
        float s = v0.x * q0.x + v0.y * q0.y + v0.z * q0.z + v0.w * q0.w
                + v1.x * q1.x + v1.y * q1.y + v1.z * q1.z + v1.w * q1.w;
#pragma unroll
        for (int o = 16; o; o >>= 1) s += __shfl_xor_sync(0xFFFFFFFFu, s, o);
        if (!lane) sp->a.sc[l] = s;
        v0 = n0; v1 = n1; l = ln;
    }
    __syncthreads();
    if (tid < 128) sp->a.part[tid] = sp->a.sc[tid];
    __syncthreads();
    for (int s = 64; s; s >>= 1) {
        if (tid < s) sp->a.part[tid] = fmaxf(sp->a.part[tid], sp->a.part[tid + s]);
        __syncthreads();
    }
    float mx = sp->a.part[0];
    __syncthreads();
    if (tid < 128) {
        float e = (tid < Lq) ? __expf(sp->a.sc[tid] - mx) : 0.f;
        sp->a.sc[tid] = e; sp->a.part[tid] = e;
    }
    __syncthreads();
    for (int s = 64; s; s >>= 1) {
        if (tid < s) sp->a.part[tid] += sp->a.part[tid + s];
        __syncthreads();
    }
    float inv = 1.f / sp->a.part[0];
    __syncthreads();
    // context: halves of L, 256 cols each half
    int col = tid & 255, half = tid >> 8;
    float acc = 0.f;
    int l0 = half * 50;
#pragma unroll 5
    for (int l2 = l0; l2 < l0 + 50; l2++) acc += sp->a.sc[l2] * sp->a.tile[l2 * 256 + col];
    sp->a.part[tid] = acc;
    __syncthreads();
    if (tid < 256) ctx_att[b * 256 + tid] = (sp->a.part[tid] + sp->a.part[tid + 256]) * inv;
    __syncthreads();
}

// ---------------- finalize: two rows per iteration ----------------
__device__ void finalize_pair(SPool* sp, int pr, int t, const float* __restrict__ logit,
                              const float* __restrict__ Q, const int* __restrict__ actions,
                              float* __restrict__ out) {
    const int tid = threadIdx.x;
    const int col = tid & 255, half = tid >> 8;
    const int b = pr * 2 + half;
    float x = logit[b * 256 + col];
    sp->f.part[tid] = x; __syncthreads();
    for (int s = 128; s; s >>= 1) {
        if (col < s) sp->f.part[tid] = fmaxf(sp->f.part[tid], sp->f.part[tid + s]);
        __syncthreads();
    }
    float mx = sp->f.part[half * 256];
    __syncthreads();
    float e = __expf(x - mx);
    sp->f.part[tid] = e; __syncthreads();
    for (int s = 128; s; s >>= 1) {
        if (col < s) sp->f.part[tid] += sp->f.part[tid + s];
        __syncthreads();
    }
    float pi = e / sp->f.part[half * 256];
    __syncthreads();
    out[(size_t)Bq * Lq + ((size_t)b * Lq + t) * 256 + col] = pi;
    sp->f.part[tid] = pi * Q[b * 256 + col];
    __syncthreads();
    for (int s = 128; s; s >>= 1) {
        if (col < s) sp->f.part[tid] += sp->f.part[tid + s];
        __syncthreads();
    }
    if (col == 0) {
        out[(size_t)Bq * Lq + (size_t)Bq * Lq * 256 + b * Lq + t] = sp->f.part[half * 256];
        out[b * Lq + t] = (float)actions[b * Lq + t];
    }
    __syncthreads();
}

// ---------------- persistent mega-kernel ----------------
__global__ void __launch_bounds__(NTHR, 1)
mega(const float* __restrict__ enc_out, const float* __restrict__ enc_h,
     const float* __restrict__ enc_c, const float* __restrict__ emb,
     const float* __restrict__ Wih0, const float* __restrict__ Whh0,
     const float* __restrict__ bih0, const float* __restrict__ bhh0,
     const float* __restrict__ Wih1, const float* __restrict__ Whh1,
     const float* __restrict__ bih1, const float* __restrict__ bhh1,
     const float* __restrict__ Wa, const float* __restrict__ Wconcat,
     const float* __restrict__ Wout, const float* __restrict__ Wcrit,
     const float* __restrict__ bcrit, const int* __restrict__ actions,
     float* __restrict__ out) {
    extern __shared__ float dynsm[];
    SPool* sp = (SPool*)dynsm;
    __shared__ int gidx[128];
    const int bid = blockIdx.x, tid = threadIdx.x;
    unsigned bt = 0;

    // ---- phase 0: weight permute + transposes + state init ----
    for (int idx = bid * NTHR + tid; idx < 1024 * 768; idx += NBLK * NTHR) {
        int n = idx / 768, k = idx - n * 768;
        int h = n >> 2, g = n & 3, orow = g * 256 + h;
        g_Wp0[idx] = (k < 512) ? Wih0[orow * 512 + k] : Whh0[orow * 256 + (k - 512)];
    }
    for (int idx = bid * NTHR + tid; idx < 1024 * 512; idx += NBLK * NTHR) {
        int n = idx / 512, k = idx - n * 512;
        int h = n >> 2, g = n & 3, orow = g * 256 + h;
        g_Wp1[idx] = (k < 256) ? Wih1[orow * 256 + k] : Whh1[orow * 256 + (k - 256)];
    }
    for (int idx = bid * NTHR + tid; idx < 65536; idx += NBLK * NTHR) {
        int k = idx >> 8, h = idx & 255;
        g_WaT[idx] = Wa[h * 256 + k];          // WaT[k][h] = Wa[h][k]
    }
    for (int idx = bid * NTHR + tid; idx < 1024; idx += NBLK * NTHR) {
        int h = idx >> 2, g = idx & 3, orow = g * 256 + h;
        g_b0p[idx] = bih0[orow] + bhh0[orow];
        g_b1p[idx] = bih1[orow] + bhh1[orow];
    }
    for (int idx = bid * NTHR + tid; idx < Bq * 256; idx += NBLK * NTHR) {
        g_h0a[idx] = enc_h[idx]; g_h1a[idx] = enc_h[Bq * 256 + idx];
        g_c0[idx] = enc_c[idx];  g_c1[idx] = enc_c[Bq * 256 + idx];
        int b = idx >> 8, hh = idx & 255;
        const float* p = enc_out + (size_t)b * Lq * 256 + hh;
        float s = 0.f;
        for (int l = 0; l < Lq; l++) s += p[(size_t)l * 256];
        g_ctx[idx] = s * (1.0f / Lq);
    }
    bt += NBLK; gsync(bt);

    float *h0c = g_h0a, *h0n = g_h0b, *h1c = g_h1a, *h1n = g_h1b;
    const int bmL = (bid >> 4) * 128, bnL = (bid & 15) * 64;   // lstm tiles
    const int bmS = (bid >> 3) * 64,  bnS = (bid & 7) * 32;    // small tiles

    for (int t = 0; t < Lq; t++) {
        // phase 1: LSTM0 (emb gather | ctx | h0) -> h0n, c0
        if (tid < 128)
            gidx[tid] = (t == 0) ? 0 : actions[(bmL + tid) * Lq + (t - 1)];
        __syncthreads();
        lstm_gemm(sp, gidx, bmL, bnL, emb, g_ctx, h0c, 768, true,
                  g_Wp0, g_b0p, g_c0, h0n);
        bt += NBLK; gsync(bt);
        // phase 2: LSTM1 (h0n | h1) -> h1n, c1
        lstm_gemm(sp, gidx, bmL, bnL, h0n, h1c, nullptr, 512, false,
                  g_Wp1, g_b1p, g_c1, h1n);
        bt += NBLK; gsync(bt);
        // phase 3: q = h1 @ Wa
        gemm_small(sp, bmS, bnS, h1n, nullptr, 256, g_WaT, nullptr, 0, g_q);
        bt += NBLK; gsync(bt);
        // phase 4: attention (8 rows per block)
        for (int b = bid; b < Bq; b += NBLK)
            attention_row(sp, b, g_q, enc_out, g_ctx_att);
        bt += NBLK; gsync(bt);
        // phase 5: ctx = tanh([h1 | ctx_att] @ Wconcat^T)
        gemm_small(sp, bmS, bnS, h1n, g_ctx_att, 512, Wconcat, nullptr, 1, g_ctx);
        bt += NBLK; gsync(bt);
        // phase 6: logit = ctx @ Wout^T
        gemm_small(sp, bmS, bnS, g_ctx, nullptr, 256, Wout, nullptr, 0, g_logit);
        bt += NBLK; gsync(bt);
        // phase 7: Q = logit @ Wcrit^T + bcrit
        gemm_small(sp, bmS, bnS, g_logit, nullptr, 256, Wcrit, bcrit, 0, g_Q);
        bt += NBLK; gsync(bt);
        // phase 8: finalize (4 pair-iterations per block; no trailing barrier)
        for (int pr = bid; pr < 512; pr += NBLK)
            finalize_pair(sp, pr, t, g_logit, g_Q, actions, out);
        float* tmp = h0c; h0c = h0n; h0n = tmp;
        tmp = h1c; h1c = h1n; h1n = tmp;
    }
}

__global__ void reset_k() { g_count = 0; }

// ---------------- host ----------------
extern "C" void kernel_launch(void* const* d_in, const int* in_sizes, int n_in,
                              void* d_out, int out_size) {
    const float* enc_out = (const float*)d_in[0];
    const float* enc_h   = (const float*)d_in[1];
    const float* enc_c   = (const float*)d_in[2];
    const float* emb     = (const float*)d_in[3];
    const float* Wih0    = (const float*)d_in[4];
    const float* Whh0    = (const float*)d_in[5];
    const float* bih0    = (const float*)d_in[6];
    const float* bhh0    = (const float*)d_in[7];
    const float* Wih1    = (const float*)d_in[8];
    const float* Whh1    = (const float*)d_in[9];
    const float* bih1    = (const float*)d_in[10];
    const float* bhh1    = (const float*)d_in[11];
    const float* Wa      = (const float*)d_in[12];
    const float* Wconcat = (const float*)d_in[13];
    const float* Wout    = (const float*)d_in[14];
    const float* Wcrit   = (const float*)d_in[15];
    const float* bcrit   = (const float*)d_in[16];
    const int*   actions = (const int*)d_in[17];
    float* out = (float*)d_out;

    const int smem = (int)sizeof(SPool);
    cudaFuncSetAttribute(mega, cudaFuncAttributeMaxDynamicSharedMemorySize, smem);
    reset_k<<<1, 1>>>();
    mega<<<NBLK, NTHR, smem>>>(enc_out, enc_h, enc_c, emb,
                               Wih0, Whh0, bih0, bhh0,
                               Wih1, Whh1, bih1, bhh1,
                               Wa, Wconcat, Wout, Wcrit, bcrit, actions, out);
}